// round 1
// baseline (speedup 1.0000x reference)
#include <cuda_runtime.h>
#include <math.h>

// ----------------------------------------------------------------------------
// VisionExperts: 3-expert vision MoE.
//   x [64,3,448,448] fp32 -> per-expert: resize -> patch-embed GEMM ->
//   grid-resize(32x32) -> projector GEMM -> gated sum into out [64,1024,1024].
//
// Pipeline (all on default stream, graph-capturable):
//   1) gate_kernel: w[e][b] from selected_experts / routing_weights
//   2) memset d_out = 0
//   3) per expert e in {0,1,2} (sequential):
//        (e==1) resize input 448->336
//        im2col -> g_patches
//        gemm (mode 0): feat = patches @ w_tower + b_tower     [gated skip]
//        (e!=0) resize feature grid g->32 -> g_resized          [gated skip]
//        gemm (mode 1): out += w[e][b] * (A @ w_proj + b_proj)  [gated skip]
// ----------------------------------------------------------------------------

// ---------------- scratch (static device globals; no allocs) ----------------
__device__ float g_gate[3 * 64];                      // [expert][batch]
__device__ float g_x336[64LL * 3 * 336 * 336];        // expert-1 resized input
__device__ float g_patches[38535168];                 // im2col buffer (max over experts)
__device__ float g_feat[67108864];                    // tower output [b, gg, C] (max)
__device__ float g_resized[75497472];                 // grid-resized tokens [b,1024,C] (max)

// ---------------- gates ----------------
__global__ void gate_kernel(const int* __restrict__ sel, const float* __restrict__ rw) {
    int b = threadIdx.x;
    if (b >= 64) return;
    float w0 = 0.f, w1 = 0.f, w2 = 0.f;
#pragma unroll
    for (int k = 0; k < 2; k++) {
        int e = sel[b * 2 + k];
        float r = rw[b * 2 + k];
        w0 += (e == 0) ? r : 0.f;
        w1 += (e == 1) ? r : 0.f;
        w2 += (e == 2) ? r : 0.f;
    }
    g_gate[b] = w0;
    g_gate[64 + b] = w1;
    g_gate[128 + b] = w2;
}

// ---------------- input resize 448 -> 336 (align_corners bilinear) ----------
__global__ void resize_input_kernel(const float* __restrict__ x) {
    long long idx = (long long)blockIdx.x * blockDim.x + threadIdx.x;
    const long long total = 64LL * 3 * 336 * 336;
    if (idx >= total) return;
    int ox = (int)(idx % 336);
    long long r = idx / 336;
    int oy = (int)(r % 336); r /= 336;
    int c = (int)(r % 3);
    int b = (int)(r / 3);
    if (g_gate[64 + b] == 0.f) return;  // only expert-1 consumers
    const float sc = 447.0f / 335.0f;
    float ys = oy * sc, xs = ox * sc;
    int y0 = (int)floorf(ys); int y1 = min(y0 + 1, 447);
    int x0 = (int)floorf(xs); int x1 = min(x0 + 1, 447);
    float ty = ys - (float)y0, tx = xs - (float)x0;
    const float* p = x + ((long long)(b * 3 + c)) * 448 * 448;
    float a = p[y0 * 448 + x0], bv = p[y0 * 448 + x1];
    float cv = p[y1 * 448 + x0], dv = p[y1 * 448 + x1];
    float r0 = a * (1.f - ty) + cv * ty;
    float r1 = bv * (1.f - ty) + dv * ty;
    g_x336[idx] = r0 * (1.f - tx) + r1 * tx;
}

// ---------------- im2col: src [64,3,s,s] -> patches [64*g*g, 3*p*p] ---------
__global__ void im2col_kernel(const float* __restrict__ src, int s, int p, int g) {
    const int K = 3 * p * p;
    const int gg = g * g;
    long long idx = (long long)blockIdx.x * blockDim.x + threadIdx.x;
    long long total = 64LL * gg * K;
    if (idx >= total) return;
    int k = (int)(idx % K);
    long long row = idx / K;
    int t = (int)(row % gg);
    int b = (int)(row / gg);
    int ty = t / g, tx = t % g;
    int ch = k / (p * p);
    int rr = k % (p * p);
    int py = rr / p, px = rr % p;
    g_patches[idx] = src[(((long long)b * 3 + ch) * s + (ty * p + py)) * s + (tx * p + px)];
}

// ---------------- feature-grid resize g -> 32, token-major output ----------
// feat [b, g*g, C] -> out [b, 1024, C]
__global__ void resize_grid_kernel(const float* __restrict__ feat, float* __restrict__ outp,
                                   int g, int C, const float* __restrict__ gate) {
    long long idx = (long long)blockIdx.x * blockDim.x + threadIdx.x;
    long long total = 64LL * 1024 * C;
    if (idx >= total) return;
    int ch = (int)(idx % C);
    long long r = idx / C;
    int ot = (int)(r % 1024);
    int b = (int)(r / 1024);
    if (gate[b] == 0.f) return;
    int oy = ot >> 5, ox = ot & 31;
    float sc = (float)(g - 1) / 31.0f;
    float ys = oy * sc, xs = ox * sc;
    int y0 = (int)floorf(ys); int y1 = min(y0 + 1, g - 1);
    int x0 = (int)floorf(xs); int x1 = min(x0 + 1, g - 1);
    float ty = ys - (float)y0, tx = xs - (float)x0;
    const float* fb = feat + (long long)b * g * g * C;
    float a = fb[(long long)(y0 * g + x0) * C + ch];
    float bv = fb[(long long)(y0 * g + x1) * C + ch];
    float cv = fb[(long long)(y1 * g + x0) * C + ch];
    float dv = fb[(long long)(y1 * g + x1) * C + ch];
    float r0 = a * (1.f - ty) + cv * ty;
    float r1 = bv * (1.f - ty) + dv * ty;
    outp[idx] = r0 * (1.f - tx) + r1 * tx;
}

// ---------------- fp32 tiled GEMM: C = A[M,K] @ W[K,N] + bias --------------
// mode 0: C = acc + bias                        (tower; gated block-skip only)
// mode 1: C += gate[row/gg] * (acc + bias)      (projector; per-row gate)
// Requirements: M % 128 == 0, N % 128 == 0, K % 4 == 0.
__global__ __launch_bounds__(256, 2) void gemm_kernel(
    const float* __restrict__ A, const float* __restrict__ W,
    const float* __restrict__ bias, float* __restrict__ C,
    int M, int N, int K, int gg, const float* __restrict__ gate, int accmode)
{
    const int row0 = blockIdx.y * 128;
    const int col0 = blockIdx.x * 128;

    // gated block skip: all samples covered by this row tile inactive -> exit
    {
        int b0 = row0 / gg, b1 = (row0 + 127) / gg;
        float gm = 0.f;
        for (int b = b0; b <= b1; b++) gm = fmaxf(gm, gate[b]);
        if (gm == 0.f) return;
    }

    __shared__ float As[8][128];
    __shared__ float Bs[8][128];

    const int tid = threadIdx.x;
    const int tr = tid >> 4;       // 0..15 (row group)
    const int tc = tid & 15;       // 0..15 (col group)

    float acc[8][8];
#pragma unroll
    for (int i = 0; i < 8; i++)
#pragma unroll
        for (int j = 0; j < 8; j++) acc[i][j] = 0.f;

    const int am = tid >> 1;            // 0..127 : A row within tile
    const int ak = (tid & 1) * 4;       // 0 or 4 : A k offset
    const int bk = tid >> 5;            // 0..7   : W k row
    const int bn = (tid & 31) * 4;      // col offset

    for (int kt = 0; kt < K; kt += 8) {
        float4 av = make_float4(0.f, 0.f, 0.f, 0.f);
        if (kt + ak < K)
            av = *reinterpret_cast<const float4*>(&A[(long long)(row0 + am) * K + kt + ak]);
        As[ak + 0][am] = av.x; As[ak + 1][am] = av.y;
        As[ak + 2][am] = av.z; As[ak + 3][am] = av.w;

        float4 bv = make_float4(0.f, 0.f, 0.f, 0.f);
        if (kt + bk < K)
            bv = *reinterpret_cast<const float4*>(&W[(long long)(kt + bk) * N + col0 + bn]);
        *reinterpret_cast<float4*>(&Bs[bk][bn]) = bv;

        __syncthreads();
#pragma unroll
        for (int kk = 0; kk < 8; kk++) {
            float a8[8], b8[8];
#pragma unroll
            for (int i = 0; i < 8; i++) a8[i] = As[kk][tr * 8 + i];
#pragma unroll
            for (int j = 0; j < 8; j++) b8[j] = Bs[kk][tc * 8 + j];
#pragma unroll
            for (int i = 0; i < 8; i++)
#pragma unroll
                for (int j = 0; j < 8; j++)
                    acc[i][j] = fmaf(a8[i], b8[j], acc[i][j]);
        }
        __syncthreads();
    }

    if (accmode == 0) {
#pragma unroll
        for (int i = 0; i < 8; i++) {
            int row = row0 + tr * 8 + i;
#pragma unroll
            for (int j = 0; j < 8; j++) {
                int col = col0 + tc * 8 + j;
                C[(long long)row * N + col] = acc[i][j] + bias[col];
            }
        }
    } else {
#pragma unroll
        for (int i = 0; i < 8; i++) {
            int row = row0 + tr * 8 + i;
            float w = gate[row / gg];
            if (w != 0.f) {
#pragma unroll
                for (int j = 0; j < 8; j++) {
                    int col = col0 + tc * 8 + j;
                    C[(long long)row * N + col] += w * (acc[i][j] + bias[col]);
                }
            }
        }
    }
}

// ---------------- launch ----------------
static inline int nblk(long long total, int t) { return (int)((total + t - 1) / t); }

extern "C" void kernel_launch(void* const* d_in, const int* in_sizes, int n_in,
                              void* d_out, int out_size) {
    const float* x   = (const float*)d_in[0];
    const int*   sel = (const int*)d_in[1];
    const float* rw  = (const float*)d_in[2];
    const float* wt0 = (const float*)d_in[3];  const float* bt0 = (const float*)d_in[4];
    const float* wp0 = (const float*)d_in[5];  const float* bp0 = (const float*)d_in[6];
    const float* wt1 = (const float*)d_in[7];  const float* bt1 = (const float*)d_in[8];
    const float* wp1 = (const float*)d_in[9];  const float* bp1 = (const float*)d_in[10];
    const float* wt2 = (const float*)d_in[11]; const float* bt2 = (const float*)d_in[12];
    const float* wp2 = (const float*)d_in[13]; const float* bp2 = (const float*)d_in[14];
    float* out = (float*)d_out;

    float *gate_d, *x336_d, *patches_d, *feat_d, *resized_d;
    cudaGetSymbolAddress((void**)&gate_d,    g_gate);
    cudaGetSymbolAddress((void**)&x336_d,    g_x336);
    cudaGetSymbolAddress((void**)&patches_d, g_patches);
    cudaGetSymbolAddress((void**)&feat_d,    g_feat);
    cudaGetSymbolAddress((void**)&resized_d, g_resized);

    gate_kernel<<<1, 64>>>(sel, rw);
    cudaMemsetAsync(d_out, 0, (size_t)out_size * sizeof(float));

    // ---- expert 1 input resize (needs gates) ----
    resize_input_kernel<<<nblk(64LL * 3 * 336 * 336, 256), 256>>>(x);

    // ================= expert 0: s=448, p=14, g=32, K=588, C=1024 =========
    im2col_kernel<<<nblk(64LL * 1024 * 588, 256), 256>>>(x, 448, 14, 32);
    gemm_kernel<<<dim3(1024 / 128, 65536 / 128), 256>>>(
        patches_d, wt0, bt0, feat_d, 65536, 1024, 588, 1024, gate_d + 0, 0);
    // g == 32: grid resize is identity -> project straight from feat
    gemm_kernel<<<dim3(1024 / 128, 65536 / 128), 256>>>(
        feat_d, wp0, bp0, out, 65536, 1024, 1024, 1024, gate_d + 0, 1);

    // ================= expert 1: s=336, p=14, g=24, K=588, C=768 ==========
    im2col_kernel<<<nblk(64LL * 576 * 588, 256), 256>>>(x336_d, 336, 14, 24);
    gemm_kernel<<<dim3(768 / 128, 36864 / 128), 256>>>(
        patches_d, wt1, bt1, feat_d, 36864, 768, 588, 576, gate_d + 64, 0);
    resize_grid_kernel<<<nblk(64LL * 1024 * 768, 256), 256>>>(
        feat_d, resized_d, 24, 768, gate_d + 64);
    gemm_kernel<<<dim3(1024 / 128, 65536 / 128), 256>>>(
        resized_d, wp1, bp1, out, 65536, 1024, 768, 1024, gate_d + 64, 1);

    // ================= expert 2: s=448, p=32, g=14, K=3072, C=1152 ========
    im2col_kernel<<<nblk(64LL * 196 * 3072, 256), 256>>>(x, 448, 32, 14);
    gemm_kernel<<<dim3(1152 / 128, 12544 / 128), 256>>>(
        patches_d, wt2, bt2, feat_d, 12544, 1152, 3072, 196, gate_d + 128, 0);
    resize_grid_kernel<<<nblk(64LL * 1024 * 1152, 256), 256>>>(
        feat_d, resized_d, 14, 1152, gate_d + 128);
    gemm_kernel<<<dim3(1024 / 128, 65536 / 128), 256>>>(
        resized_d, wp2, bp2, out, 65536, 1024, 1152, 1024, gate_d + 128, 1);
}

// round 3
// speedup vs baseline: 2.0889x; 2.0889x over previous
#include <cuda_runtime.h>
#include <cuda_bf16.h>
#include <cstdint>
#include <math.h>

// ============================================================================
// VisionExperts via mma.sync (HMMA bf16, sm_80+ ISA — no sm_103a-only PTX).
// fp32 -> (hi,lo) bf16 split; GEMM accumulates Ah*Bh + Ah*Bl + Al*Bh in fp32.
// 128x128x32 CTA tiles, 8 warps (2x4, warp tile 64x32), cp.async double buffer,
// XOR-swizzled smem rows (128B = hi|lo) for conflict-free ldmatrix.
// ============================================================================

// ---------------- scratch (device globals; no allocs) ----------------
__device__ float g_gate[3 * 64];
__device__ float g_x336[21676032];                        // expert-1 resized input
__device__ float g_feat[28311552];                        // tower fp32 out (e1/e2)
__device__ __align__(128) __nv_bfloat16 g_A1h[41943040];  // tower A operand
__device__ __align__(128) __nv_bfloat16 g_A1l[41943040];
__device__ __align__(128) __nv_bfloat16 g_A2h[75497472];  // projector A operand
__device__ __align__(128) __nv_bfloat16 g_A2l[75497472];
__device__ __align__(128) __nv_bfloat16 g_Bh[3538944];    // weight (N-major)
__device__ __align__(128) __nv_bfloat16 g_Bl[3538944];

// ---------------- helpers ----------------
__device__ __forceinline__ uint32_t smem_u32(const void* p) {
    uint32_t a;
    asm("{ .reg .u64 t; cvta.to.shared.u64 t, %1; cvt.u32.u64 %0, t; }" : "=r"(a) : "l"(p));
    return a;
}
__device__ __forceinline__ void cp16(uint32_t so, const void* g) {
    asm volatile("cp.async.cg.shared.global [%0], [%1], 16;" :: "r"(so), "l"(g));
}
__device__ __forceinline__ void ldm4(uint32_t* r, uint32_t addr) {
    asm volatile("ldmatrix.sync.aligned.m8n8.x4.shared.b16 {%0,%1,%2,%3}, [%4];"
                 : "=r"(r[0]), "=r"(r[1]), "=r"(r[2]), "=r"(r[3]) : "r"(addr));
}
__device__ __forceinline__ void mma_bf16(float* d, const uint32_t* a, uint32_t b0, uint32_t b1) {
    asm volatile("mma.sync.aligned.m16n8k16.row.col.f32.bf16.bf16.f32 "
                 "{%0,%1,%2,%3}, {%4,%5,%6,%7}, {%8,%9}, {%0,%1,%2,%3};"
                 : "+f"(d[0]), "+f"(d[1]), "+f"(d[2]), "+f"(d[3])
                 : "r"(a[0]), "r"(a[1]), "r"(a[2]), "r"(a[3]), "r"(b0), "r"(b1));
}
__device__ __forceinline__ void split2(float v, __nv_bfloat16& h, __nv_bfloat16& l) {
    h = __float2bfloat16(v);
    l = __float2bfloat16(v - __bfloat162float(h));
}

// ---------------- gates ----------------
__global__ void gate_kernel(const int* __restrict__ sel, const float* __restrict__ rw) {
    int b = threadIdx.x;
    if (b >= 64) return;
    float w0 = 0.f, w1 = 0.f, w2 = 0.f;
#pragma unroll
    for (int k = 0; k < 2; k++) {
        int e = sel[b * 2 + k];
        float r = rw[b * 2 + k];
        w0 += (e == 0) ? r : 0.f;
        w1 += (e == 1) ? r : 0.f;
        w2 += (e == 2) ? r : 0.f;
    }
    g_gate[b] = w0; g_gate[64 + b] = w1; g_gate[128 + b] = w2;
}

// ---------------- input resize 448 -> 336 ----------------
__global__ void resize_input_kernel(const float* __restrict__ x) {
    long long idx = (long long)blockIdx.x * blockDim.x + threadIdx.x;
    const long long total = 64LL * 3 * 336 * 336;
    if (idx >= total) return;
    int ox = (int)(idx % 336);
    long long r = idx / 336;
    int oy = (int)(r % 336); r /= 336;
    int c = (int)(r % 3);
    int b = (int)(r / 3);
    if (g_gate[64 + b] == 0.f) return;
    const float sc = 447.0f / 335.0f;
    float ys = oy * sc, xs = ox * sc;
    int y0 = (int)floorf(ys); int y1 = min(y0 + 1, 447);
    int x0 = (int)floorf(xs); int x1 = min(x0 + 1, 447);
    float ty = ys - (float)y0, tx = xs - (float)x0;
    const float* p = x + ((long long)(b * 3 + c)) * 448 * 448;
    float a = p[y0 * 448 + x0], bv = p[y0 * 448 + x1];
    float cv = p[y1 * 448 + x0], dv = p[y1 * 448 + x1];
    float r0 = a * (1.f - ty) + cv * ty;
    float r1 = bv * (1.f - ty) + dv * ty;
    g_x336[idx] = r0 * (1.f - tx) + r1 * tx;
}

// ---------------- weight transpose + split:  W[K,N] -> B[N,Kp] hi/lo --------
__global__ void weight_splitT(const float* __restrict__ W, int K, int N, int Kp,
                              __nv_bfloat16* __restrict__ Bh, __nv_bfloat16* __restrict__ Bl) {
    long long idx = (long long)blockIdx.x * blockDim.x + threadIdx.x;
    long long total = (long long)N * Kp;
    if (idx >= total) return;
    int k = (int)(idx % Kp);
    int n = (int)(idx / Kp);
    float v = (k < K) ? W[(long long)k * N + n] : 0.f;
    __nv_bfloat16 h, l; split2(v, h, l);
    Bh[idx] = h; Bl[idx] = l;
}

// ---------------- im2col + split ----------------
__global__ void im2col_split(const float* __restrict__ src, int s, int p, int g, int Kp,
                             const float* __restrict__ gate,
                             __nv_bfloat16* __restrict__ Ah, __nv_bfloat16* __restrict__ Al) {
    const int K = 3 * p * p, gg = g * g;
    long long idx = (long long)blockIdx.x * blockDim.x + threadIdx.x;
    long long total = 64LL * gg * Kp;
    if (idx >= total) return;
    int k = (int)(idx % Kp);
    long long row = idx / Kp;
    int t = (int)(row % gg);
    int b = (int)(row / gg);
    if (gate[b] == 0.f) return;
    float v = 0.f;
    if (k < K) {
        int ch = k / (p * p), rr = k % (p * p);
        int py = rr / p, px = rr % p;
        int ty = t / g, tx = t % g;
        v = src[(((long long)b * 3 + ch) * s + (ty * p + py)) * s + (tx * p + px)];
    }
    __nv_bfloat16 h, l; split2(v, h, l);
    Ah[idx] = h; Al[idx] = l;
}

// ---------------- grid resize g->32 + split ----------------
__global__ void resize_grid_split(const float* __restrict__ feat, int g, int C,
                                  const float* __restrict__ gate,
                                  __nv_bfloat16* __restrict__ Ah, __nv_bfloat16* __restrict__ Al) {
    long long idx = (long long)blockIdx.x * blockDim.x + threadIdx.x;
    long long total = 64LL * 1024 * C;
    if (idx >= total) return;
    int ch = (int)(idx % C);
    long long r = idx / C;
    int ot = (int)(r % 1024);
    int b = (int)(r / 1024);
    if (gate[b] == 0.f) return;
    int oy = ot >> 5, ox = ot & 31;
    float sc = (float)(g - 1) / 31.0f;
    float ys = oy * sc, xs = ox * sc;
    int y0 = (int)floorf(ys); int y1 = min(y0 + 1, g - 1);
    int x0 = (int)floorf(xs); int x1 = min(x0 + 1, g - 1);
    float ty = ys - (float)y0, tx = xs - (float)x0;
    const float* fb = feat + (long long)b * g * g * C;
    float a = fb[(long long)(y0 * g + x0) * C + ch];
    float bv = fb[(long long)(y0 * g + x1) * C + ch];
    float cv = fb[(long long)(y1 * g + x0) * C + ch];
    float dv = fb[(long long)(y1 * g + x1) * C + ch];
    float r0 = a * (1.f - ty) + cv * ty;
    float r1 = bv * (1.f - ty) + dv * ty;
    float v = r0 * (1.f - tx) + r1 * tx;
    __nv_bfloat16 h, l; split2(v, h, l);
    Ah[idx] = h; Al[idx] = l;
}

// ---------------- HMMA GEMM ----------------
// D = (Ah+Al) @ (Bh+Bl)^T (dropping Al*Bl), fp32 accumulate.
// outmode 0: outF = acc + bias
// outmode 1: outF += gate[row/gg] * (acc + bias)
// outmode 2: split(acc + bias) -> outH/outL
// M,N multiples of 128; Kp multiple of 32.
__global__ void __launch_bounds__(256, 1) gemm_mma(
    const __nv_bfloat16* __restrict__ Ah, const __nv_bfloat16* __restrict__ Al,
    const __nv_bfloat16* __restrict__ Bh, const __nv_bfloat16* __restrict__ Bl,
    const float* __restrict__ bias, int M, int N, int Kp,
    const float* __restrict__ gate, int gg, int outmode,
    float* __restrict__ outF, __nv_bfloat16* __restrict__ outH, __nv_bfloat16* __restrict__ outL)
{
    const int row0 = blockIdx.y * 128;
    const int col0 = blockIdx.x * 128;
    {   // gated tile skip
        int b0 = row0 / gg, b1 = (row0 + 127) / gg;
        float gm = 0.f;
        for (int b = b0; b <= b1; b++) gm = fmaxf(gm, gate[b]);
        if (gm == 0.f) return;
    }

    extern __shared__ char smem[];
    const uint32_t S = smem_u32(smem);
    const int tid = threadIdx.x;
    const int wid = tid >> 5, lane = tid & 31;
    const int wm = (wid >> 2) * 64;     // warp m offset (2 rows of warps)
    const int wn = (wid & 3) * 32;      // warp n offset (4 cols of warps)
    const int NC = Kp >> 5;

    // smem stage: A region 128 rows x 128B (Ah 64B | Al 64B), then B likewise.
    // row layout: 8 chunks of 16B; chunk j stored at (j ^ (row&7)).
    auto prefetch = [&](int c, int s) {
        uint32_t SA = S + (uint32_t)s * 32768u;
        uint32_t SB = SA + 16384u;
        int kt = c << 5;
#pragma unroll
        for (int i = 0; i < 8; i++) {
            int cid = tid + (i << 8);
            int isB = cid >> 10;            // uniform across warp per i
            int rem = cid & 1023;
            int r = rem >> 3, j = rem & 7;
            const __nv_bfloat16* gp;
            if (!isB) gp = ((j < 4) ? Ah : Al) + (size_t)(row0 + r) * Kp + kt + (j & 3) * 8;
            else      gp = ((j < 4) ? Bh : Bl) + (size_t)(col0 + r) * Kp + kt + (j & 3) * 8;
            uint32_t so = (isB ? SB : SA) + r * 128 + ((j ^ (r & 7)) << 4);
            cp16(so, gp);
        }
        asm volatile("cp.async.commit_group;" ::: "memory");
    };

    float acc[4][4][4];
#pragma unroll
    for (int i = 0; i < 4; i++)
#pragma unroll
        for (int j = 0; j < 4; j++)
#pragma unroll
            for (int q = 0; q < 4; q++) acc[i][j][q] = 0.f;

    const int lrow = ((lane >> 3) & 1) * 8 + (lane & 7);  // row within 16-row block
    const int lchunk = lane >> 4;                          // 0/1: k-chunk select

    prefetch(0, 0);
    for (int c = 0; c < NC; c++) {
        if (c + 1 < NC) {
            prefetch(c + 1, (c + 1) & 1);
            asm volatile("cp.async.wait_group 1;" ::: "memory");
        } else {
            asm volatile("cp.async.wait_group 0;" ::: "memory");
        }
        __syncthreads();

        uint32_t SA = S + (uint32_t)(c & 1) * 32768u;
        uint32_t SB = SA + 16384u;

#pragma unroll
        for (int kk = 0; kk < 2; kk++) {
            const int chH = kk * 2 + lchunk;       // hi chunks 0..3
            const int chL = 4 + kk * 2 + lchunk;   // lo chunks 4..7

            uint32_t bh[2][4], bl[2][4];
#pragma unroll
            for (int j2 = 0; j2 < 2; j2++) {
                int rowB = wn + j2 * 16 + lrow;
                ldm4(bh[j2], SB + rowB * 128 + ((chH ^ (rowB & 7)) << 4));
                ldm4(bl[j2], SB + rowB * 128 + ((chL ^ (rowB & 7)) << 4));
            }
#pragma unroll
            for (int i = 0; i < 4; i++) {
                int rowA = wm + i * 16 + lrow;
                uint32_t ah[4], al[4];
                ldm4(ah, SA + rowA * 128 + ((chH ^ (rowA & 7)) << 4));
                ldm4(al, SA + rowA * 128 + ((chL ^ (rowA & 7)) << 4));
#pragma unroll
                for (int j2 = 0; j2 < 2; j2++) {
                    mma_bf16(acc[i][2 * j2],     ah, bh[j2][0], bh[j2][2]);
                    mma_bf16(acc[i][2 * j2 + 1], ah, bh[j2][1], bh[j2][3]);
                    mma_bf16(acc[i][2 * j2],     ah, bl[j2][0], bl[j2][2]);
                    mma_bf16(acc[i][2 * j2 + 1], ah, bl[j2][1], bl[j2][3]);
                    mma_bf16(acc[i][2 * j2],     al, bh[j2][0], bh[j2][2]);
                    mma_bf16(acc[i][2 * j2 + 1], al, bh[j2][1], bh[j2][3]);
                }
            }
        }
        __syncthreads();
    }

    // ---- epilogue ----
    const int grp = lane >> 2, qid = lane & 3;
#pragma unroll
    for (int i = 0; i < 4; i++) {
        int r0 = row0 + wm + i * 16 + grp;
        int r1 = r0 + 8;
#pragma unroll
        for (int j = 0; j < 4; j++) {
            int col = col0 + wn + j * 8 + qid * 2;
            float b0 = bias[col], b1 = bias[col + 1];
            float v00 = acc[i][j][0] + b0, v01 = acc[i][j][1] + b1;   // row r0
            float v10 = acc[i][j][2] + b0, v11 = acc[i][j][3] + b1;   // row r1
            if (outmode == 0) {
                *reinterpret_cast<float2*>(&outF[(size_t)r0 * N + col]) = make_float2(v00, v01);
                *reinterpret_cast<float2*>(&outF[(size_t)r1 * N + col]) = make_float2(v10, v11);
            } else if (outmode == 1) {
                float w0 = gate[r0 / gg], w1 = gate[r1 / gg];
                if (w0 != 0.f) {
                    float2 o = *reinterpret_cast<const float2*>(&outF[(size_t)r0 * N + col]);
                    o.x += w0 * v00; o.y += w0 * v01;
                    *reinterpret_cast<float2*>(&outF[(size_t)r0 * N + col]) = o;
                }
                if (w1 != 0.f) {
                    float2 o = *reinterpret_cast<const float2*>(&outF[(size_t)r1 * N + col]);
                    o.x += w1 * v10; o.y += w1 * v11;
                    *reinterpret_cast<float2*>(&outF[(size_t)r1 * N + col]) = o;
                }
            } else {
                __nv_bfloat16 h0, l0, h1, l1;
                __nv_bfloat162 hp, lp;
                split2(v00, h0, l0); split2(v01, h1, l1);
                hp.x = h0; hp.y = h1; lp.x = l0; lp.y = l1;
                *reinterpret_cast<__nv_bfloat162*>(&outH[(size_t)r0 * N + col]) = hp;
                *reinterpret_cast<__nv_bfloat162*>(&outL[(size_t)r0 * N + col]) = lp;
                split2(v10, h0, l0); split2(v11, h1, l1);
                hp.x = h0; hp.y = h1; lp.x = l0; lp.y = l1;
                *reinterpret_cast<__nv_bfloat162*>(&outH[(size_t)r1 * N + col]) = hp;
                *reinterpret_cast<__nv_bfloat162*>(&outL[(size_t)r1 * N + col]) = lp;
            }
        }
    }
}

// ---------------- launch ----------------
static inline int nblk(long long total, int t) { return (int)((total + t - 1) / t); }

extern "C" void kernel_launch(void* const* d_in, const int* in_sizes, int n_in,
                              void* d_out, int out_size) {
    const float* x   = (const float*)d_in[0];
    const int*   sel = (const int*)d_in[1];
    const float* rw  = (const float*)d_in[2];
    const float* wt0 = (const float*)d_in[3];  const float* bt0 = (const float*)d_in[4];
    const float* wp0 = (const float*)d_in[5];  const float* bp0 = (const float*)d_in[6];
    const float* wt1 = (const float*)d_in[7];  const float* bt1 = (const float*)d_in[8];
    const float* wp1 = (const float*)d_in[9];  const float* bp1 = (const float*)d_in[10];
    const float* wt2 = (const float*)d_in[11]; const float* bt2 = (const float*)d_in[12];
    const float* wp2 = (const float*)d_in[13]; const float* bp2 = (const float*)d_in[14];
    float* out = (float*)d_out;

    float *gate_d, *x336_d, *feat_d;
    __nv_bfloat16 *A1h, *A1l, *A2h, *A2l, *Bh, *Bl;
    cudaGetSymbolAddress((void**)&gate_d, g_gate);
    cudaGetSymbolAddress((void**)&x336_d, g_x336);
    cudaGetSymbolAddress((void**)&feat_d, g_feat);
    cudaGetSymbolAddress((void**)&A1h, g_A1h);
    cudaGetSymbolAddress((void**)&A1l, g_A1l);
    cudaGetSymbolAddress((void**)&A2h, g_A2h);
    cudaGetSymbolAddress((void**)&A2l, g_A2l);
    cudaGetSymbolAddress((void**)&Bh, g_Bh);
    cudaGetSymbolAddress((void**)&Bl, g_Bl);

    const int SMEM = 2 * 32768;
    cudaFuncSetAttribute(gemm_mma, cudaFuncAttributeMaxDynamicSharedMemorySize, SMEM);

    gate_kernel<<<1, 64>>>(sel, rw);
    cudaMemsetAsync(d_out, 0, (size_t)out_size * sizeof(float));
    resize_input_kernel<<<nblk(64LL * 3 * 336 * 336, 256), 256>>>(x);

    // =============== expert 0: g=32, Kt=588->640, C=1024 ===============
    weight_splitT<<<nblk(1024LL * 640, 256), 256>>>(wt0, 588, 1024, 640, Bh, Bl);
    im2col_split<<<nblk(64LL * 1024 * 640, 256), 256>>>(x, 448, 14, 32, 640, gate_d, A1h, A1l);
    gemm_mma<<<dim3(1024 / 128, 65536 / 128), 256, SMEM>>>(
        A1h, A1l, Bh, Bl, bt0, 65536, 1024, 640, gate_d, 1024, 2, nullptr, A2h, A2l);
    weight_splitT<<<nblk(1024LL * 1024, 256), 256>>>(wp0, 1024, 1024, 1024, Bh, Bl);
    gemm_mma<<<dim3(1024 / 128, 65536 / 128), 256, SMEM>>>(
        A2h, A2l, Bh, Bl, bp0, 65536, 1024, 1024, gate_d, 1024, 1, out, nullptr, nullptr);

    // =============== expert 1: g=24, Kt=588->640, C=768 ===============
    weight_splitT<<<nblk(768LL * 640, 256), 256>>>(wt1, 588, 768, 640, Bh, Bl);
    im2col_split<<<nblk(64LL * 576 * 640, 256), 256>>>(x336_d, 336, 14, 24, 640, gate_d + 64, A1h, A1l);
    gemm_mma<<<dim3(768 / 128, 36864 / 128), 256, SMEM>>>(
        A1h, A1l, Bh, Bl, bt1, 36864, 768, 640, gate_d + 64, 576, 0, feat_d, nullptr, nullptr);
    resize_grid_split<<<nblk(64LL * 1024 * 768, 256), 256>>>(feat_d, 24, 768, gate_d + 64, A2h, A2l);
    weight_splitT<<<nblk(1024LL * 768, 256), 256>>>(wp1, 768, 1024, 768, Bh, Bl);
    gemm_mma<<<dim3(1024 / 128, 65536 / 128), 256, SMEM>>>(
        A2h, A2l, Bh, Bl, bp1, 65536, 1024, 768, gate_d + 64, 1024, 1, out, nullptr, nullptr);

    // =============== expert 2: g=14, Kt=3072, C=1152 ===============
    weight_splitT<<<nblk(1152LL * 3072, 256), 256>>>(wt2, 3072, 1152, 3072, Bh, Bl);
    im2col_split<<<nblk(64LL * 196 * 3072, 256), 256>>>(x, 448, 32, 14, 3072, gate_d + 128, A1h, A1l);
    gemm_mma<<<dim3(1152 / 128, 12544 / 128), 256, SMEM>>>(
        A1h, A1l, Bh, Bl, bt2, 12544, 1152, 3072, gate_d + 128, 196, 0, feat_d, nullptr, nullptr);
    resize_grid_split<<<nblk(64LL * 1024 * 1152, 256), 256>>>(feat_d, 14, 1152, gate_d + 128, A2h, A2l);
    weight_splitT<<<nblk(1024LL * 1152, 256), 256>>>(wp2, 1152, 1024, 1152, Bh, Bl);
    gemm_mma<<<dim3(1024 / 128, 65536 / 128), 256, SMEM>>>(
        A2h, A2l, Bh, Bl, bp2, 65536, 1024, 1152, gate_d + 128, 1024, 1, out, nullptr, nullptr);
}

// round 4
// speedup vs baseline: 3.4789x; 1.6654x over previous
#include <cuda_runtime.h>
#include <cuda_fp16.h>
#include <cstdint>
#include <math.h>

// ============================================================================
// VisionExperts via mma.sync (HMMA fp16, f32 accum).
// B (weights) split into fp16 hi/lo; A single fp16. C = A*Bh + A*Bl.
// Error budget: A-rounding ~2^-12/sqrt(3) per GEMM stage => ~2.5e-4 total.
// GEMM: 128x128 CTA tile, K-chunk 64, 8 warps (2x4), cp.async double buffer,
// XOR-swizzled 128B smem rows, conflict-free ldmatrix.
// ============================================================================

// ---------------- scratch (device globals; no allocs) ----------------
__device__ float g_gate[3 * 64];
__device__ float g_x336[21676032];                   // expert-1 resized input
__device__ float g_feat[28311552];                   // tower fp32 out (e1/e2)
__device__ __align__(128) __half g_A1[41943040];     // tower A operand (fp16)
__device__ __align__(128) __half g_A2[75497472];     // projector A operand
__device__ __align__(128) __half g_Bh[3538944];      // weight hi (N-major)
__device__ __align__(128) __half g_Bl[3538944];      // weight lo

// ---------------- helpers ----------------
__device__ __forceinline__ uint32_t smem_u32(const void* p) {
    uint32_t a;
    asm("{ .reg .u64 t; cvta.to.shared.u64 t, %1; cvt.u32.u64 %0, t; }" : "=r"(a) : "l"(p));
    return a;
}
__device__ __forceinline__ void cp16(uint32_t so, const void* g) {
    asm volatile("cp.async.cg.shared.global [%0], [%1], 16;" :: "r"(so), "l"(g));
}
__device__ __forceinline__ void ldm4(uint32_t* r, uint32_t addr) {
    asm volatile("ldmatrix.sync.aligned.m8n8.x4.shared.b16 {%0,%1,%2,%3}, [%4];"
                 : "=r"(r[0]), "=r"(r[1]), "=r"(r[2]), "=r"(r[3]) : "r"(addr));
}
__device__ __forceinline__ void mma_f16(float* d, const uint32_t* a, uint32_t b0, uint32_t b1) {
    asm volatile("mma.sync.aligned.m16n8k16.row.col.f32.f16.f16.f32 "
                 "{%0,%1,%2,%3}, {%4,%5,%6,%7}, {%8,%9}, {%0,%1,%2,%3};"
                 : "+f"(d[0]), "+f"(d[1]), "+f"(d[2]), "+f"(d[3])
                 : "r"(a[0]), "r"(a[1]), "r"(a[2]), "r"(a[3]), "r"(b0), "r"(b1));
}

// ---------------- gates ----------------
__global__ void gate_kernel(const int* __restrict__ sel, const float* __restrict__ rw) {
    int b = threadIdx.x;
    if (b >= 64) return;
    float w0 = 0.f, w1 = 0.f, w2 = 0.f;
#pragma unroll
    for (int k = 0; k < 2; k++) {
        int e = sel[b * 2 + k];
        float r = rw[b * 2 + k];
        w0 += (e == 0) ? r : 0.f;
        w1 += (e == 1) ? r : 0.f;
        w2 += (e == 2) ? r : 0.f;
    }
    g_gate[b] = w0; g_gate[64 + b] = w1; g_gate[128 + b] = w2;
}

// ---------------- input resize 448 -> 336 ----------------
__global__ void resize_input_kernel(const float* __restrict__ x) {
    long long idx = (long long)blockIdx.x * blockDim.x + threadIdx.x;
    const long long total = 64LL * 3 * 336 * 336;
    if (idx >= total) return;
    int ox = (int)(idx % 336);
    long long r = idx / 336;
    int oy = (int)(r % 336); r /= 336;
    int c = (int)(r % 3);
    int b = (int)(r / 3);
    if (g_gate[64 + b] == 0.f) return;
    const float sc = 447.0f / 335.0f;
    float ys = oy * sc, xs = ox * sc;
    int y0 = (int)floorf(ys); int y1 = min(y0 + 1, 447);
    int x0 = (int)floorf(xs); int x1 = min(x0 + 1, 447);
    float ty = ys - (float)y0, tx = xs - (float)x0;
    const float* p = x + ((long long)(b * 3 + c)) * 448 * 448;
    float a = p[y0 * 448 + x0], bv = p[y0 * 448 + x1];
    float cv = p[y1 * 448 + x0], dv = p[y1 * 448 + x1];
    float r0 = a * (1.f - ty) + cv * ty;
    float r1 = bv * (1.f - ty) + dv * ty;
    g_x336[idx] = r0 * (1.f - tx) + r1 * tx;
}

// ---------------- weight transpose + split: W[K,N] -> Bh/Bl [N,Kp] ---------
__global__ void weight_splitT(const float* __restrict__ W, int K, int N, int Kp,
                              __half* __restrict__ Bh, __half* __restrict__ Bl) {
    long long idx = (long long)blockIdx.x * blockDim.x + threadIdx.x;
    long long total = (long long)N * Kp;
    if (idx >= total) return;
    int k = (int)(idx % Kp);
    int n = (int)(idx / Kp);
    float v = (k < K) ? W[(long long)k * N + n] : 0.f;
    __half h = __float2half_rn(v);
    __half l = __float2half_rn(v - __half2float(h));
    Bh[idx] = h; Bl[idx] = l;
}

// ---------------- im2col -> fp16 (templated; 8 elems/thread) ----------------
template <int S, int P, int G, int KP>
__global__ void im2col_half(const float* __restrict__ src, const float* __restrict__ gate,
                            __half* __restrict__ A) {
    constexpr int K = 3 * P * P;
    constexpr int GG = G * G;
    long long v8 = (long long)blockIdx.x * blockDim.x + threadIdx.x;
    const long long total8 = 64LL * GG * (KP / 8);
    if (v8 >= total8) return;
    int kc = (int)(v8 % (KP / 8));
    long long row = v8 / (KP / 8);
    int t = (int)(row % GG);
    int b = (int)(row / GG);
    if (gate[b] == 0.f) return;
    const int ty = t / G, tx = t % G;
    const float* sb = src + ((long long)b * 3) * S * S;
    __half h[8];
#pragma unroll
    for (int j = 0; j < 8; j++) {
        int k = kc * 8 + j;
        float v = 0.f;
        if (k < K) {
            int ch = k / (P * P);
            int rr = k - ch * (P * P);
            int py = rr / P, px = rr - py * P;
            v = sb[((long long)ch * S + (ty * P + py)) * S + (tx * P + px)];
        }
        h[j] = __float2half_rn(v);
    }
    *reinterpret_cast<uint4*>(&A[row * KP + kc * 8]) = *reinterpret_cast<uint4*>(h);
}

// ---------------- grid resize g->32 -> fp16 (templated; 8 ch/thread) --------
template <int G, int C>
__global__ void resize_grid_half(const float* __restrict__ feat, const float* __restrict__ gate,
                                 __half* __restrict__ A) {
    long long v8 = (long long)blockIdx.x * blockDim.x + threadIdx.x;
    const long long total8 = 64LL * 1024 * (C / 8);
    if (v8 >= total8) return;
    int cc = (int)(v8 % (C / 8));
    long long r = v8 / (C / 8);
    int ot = (int)(r % 1024);
    int b = (int)(r / 1024);
    if (gate[b] == 0.f) return;
    int oy = ot >> 5, ox = ot & 31;
    const float sc = (float)(G - 1) / 31.0f;
    float ys = oy * sc, xs = ox * sc;
    int y0 = (int)floorf(ys); int y1 = min(y0 + 1, G - 1);
    int x0 = (int)floorf(xs); int x1 = min(x0 + 1, G - 1);
    float ty = ys - (float)y0, tx = xs - (float)x0;
    const float* fb = feat + (long long)b * G * G * C + cc * 8;
    const float* p00 = fb + (long long)(y0 * G + x0) * C;
    const float* p01 = fb + (long long)(y0 * G + x1) * C;
    const float* p10 = fb + (long long)(y1 * G + x0) * C;
    const float* p11 = fb + (long long)(y1 * G + x1) * C;
    __half h[8];
#pragma unroll
    for (int j = 0; j < 8; j += 4) {
        float4 a = *reinterpret_cast<const float4*>(p00 + j);
        float4 bv = *reinterpret_cast<const float4*>(p01 + j);
        float4 cv = *reinterpret_cast<const float4*>(p10 + j);
        float4 dv = *reinterpret_cast<const float4*>(p11 + j);
        float r0, r1;
        r0 = a.x * (1.f - ty) + cv.x * ty; r1 = bv.x * (1.f - ty) + dv.x * ty;
        h[j + 0] = __float2half_rn(r0 * (1.f - tx) + r1 * tx);
        r0 = a.y * (1.f - ty) + cv.y * ty; r1 = bv.y * (1.f - ty) + dv.y * ty;
        h[j + 1] = __float2half_rn(r0 * (1.f - tx) + r1 * tx);
        r0 = a.z * (1.f - ty) + cv.z * ty; r1 = bv.z * (1.f - ty) + dv.z * ty;
        h[j + 2] = __float2half_rn(r0 * (1.f - tx) + r1 * tx);
        r0 = a.w * (1.f - ty) + cv.w * ty; r1 = bv.w * (1.f - ty) + dv.w * ty;
        h[j + 3] = __float2half_rn(r0 * (1.f - tx) + r1 * tx);
    }
    *reinterpret_cast<uint4*>(&A[((long long)(b * 1024 + ot)) * C + cc * 8]) =
        *reinterpret_cast<uint4*>(h);
}

// ---------------- HMMA GEMM: C = A @ (Bh+Bl)^T, fp32 accumulate -----------
// outmode 0: outF = acc + bias
// outmode 1: outF += gate[row/gg] * (acc + bias)
// outmode 2: outH = half(acc + bias)
// M,N multiples of 128; Kp multiple of 64.
__global__ void __launch_bounds__(256) gemm_mma(
    const __half* __restrict__ A, const __half* __restrict__ Bh, const __half* __restrict__ Bl,
    const float* __restrict__ bias, int N, int Kp,
    const float* __restrict__ gate, int gg, int outmode,
    float* __restrict__ outF, __half* __restrict__ outH)
{
    const int row0 = blockIdx.y * 128;
    const int col0 = blockIdx.x * 128;
    {   // gated tile skip
        int b0 = row0 / gg, b1 = (row0 + 127) / gg;
        float gm = 0.f;
        for (int b = b0; b <= b1; b++) gm = fmaxf(gm, gate[b]);
        if (gm == 0.f) return;
    }

    extern __shared__ char smem[];
    const uint32_t S = smem_u32(smem);
    const int tid = threadIdx.x;
    const int wid = tid >> 5, lane = tid & 31;
    const int wm = (wid >> 2) * 64;     // warp m offset
    const int wn = (wid & 3) * 32;      // warp n offset
    const int NC = Kp >> 6;             // K chunks of 64

    // stage: A (16KB) | Bh (16KB) | Bl (16KB); 128B rows, chunk j at (j^(r&7))
    auto prefetch = [&](int c, int s) {
        uint32_t st = S + (uint32_t)s * 49152u;
        int kt = c << 6;
#pragma unroll
        for (int i = 0; i < 12; i++) {
            int cid = tid + (i << 8);
            int reg = cid >> 10;           // 0:A 1:Bh 2:Bl (uniform per warp per i)
            int rem = cid & 1023;
            int r = rem >> 3, j = rem & 7;
            const __half* gp;
            if (reg == 0)      gp = A  + (size_t)(row0 + r) * Kp + kt + j * 8;
            else if (reg == 1) gp = Bh + (size_t)(col0 + r) * Kp + kt + j * 8;
            else               gp = Bl + (size_t)(col0 + r) * Kp + kt + j * 8;
            uint32_t so = st + reg * 16384 + r * 128 + ((j ^ (r & 7)) << 4);
            cp16(so, gp);
        }
        asm volatile("cp.async.commit_group;" ::: "memory");
    };

    float acc[4][4][4];
#pragma unroll
    for (int i = 0; i < 4; i++)
#pragma unroll
        for (int j = 0; j < 4; j++)
#pragma unroll
            for (int q = 0; q < 4; q++) acc[i][j][q] = 0.f;

    const int lrow = lane & 15;
    const int lchunk = lane >> 4;

    prefetch(0, 0);
    for (int c = 0; c < NC; c++) {
        if (c + 1 < NC) {
            prefetch(c + 1, (c + 1) & 1);
            asm volatile("cp.async.wait_group 1;" ::: "memory");
        } else {
            asm volatile("cp.async.wait_group 0;" ::: "memory");
        }
        __syncthreads();

        uint32_t SA = S + (uint32_t)(c & 1) * 49152u;
        uint32_t SBH = SA + 16384u;
        uint32_t SBL = SA + 32768u;

#pragma unroll
        for (int k = 0; k < 4; k++) {
            const int ch = 2 * k + lchunk;
            uint32_t bh[2][4], bl[2][4];
#pragma unroll
            for (int j2 = 0; j2 < 2; j2++) {
                int rb = wn + j2 * 16 + lrow;
                uint32_t off = rb * 128 + ((ch ^ (rb & 7)) << 4);
                ldm4(bh[j2], SBH + off);
                ldm4(bl[j2], SBL + off);
            }
#pragma unroll
            for (int i = 0; i < 4; i++) {
                int ra = wm + i * 16 + lrow;
                uint32_t a[4];
                ldm4(a, SA + ra * 128 + ((ch ^ (ra & 7)) << 4));
#pragma unroll
                for (int j2 = 0; j2 < 2; j2++) {
                    mma_f16(acc[i][2 * j2],     a, bh[j2][0], bh[j2][2]);
                    mma_f16(acc[i][2 * j2 + 1], a, bh[j2][1], bh[j2][3]);
                    mma_f16(acc[i][2 * j2],     a, bl[j2][0], bl[j2][2]);
                    mma_f16(acc[i][2 * j2 + 1], a, bl[j2][1], bl[j2][3]);
                }
            }
        }
        __syncthreads();
    }

    // ---- epilogue ----
    const int grp = lane >> 2, qid = lane & 3;
#pragma unroll
    for (int i = 0; i < 4; i++) {
        int r0 = row0 + wm + i * 16 + grp;
        int r1 = r0 + 8;
#pragma unroll
        for (int j = 0; j < 4; j++) {
            int col = col0 + wn + j * 8 + qid * 2;
            float b0 = bias[col], b1 = bias[col + 1];
            float v00 = acc[i][j][0] + b0, v01 = acc[i][j][1] + b1;   // row r0
            float v10 = acc[i][j][2] + b0, v11 = acc[i][j][3] + b1;   // row r1
            if (outmode == 0) {
                *reinterpret_cast<float2*>(&outF[(size_t)r0 * N + col]) = make_float2(v00, v01);
                *reinterpret_cast<float2*>(&outF[(size_t)r1 * N + col]) = make_float2(v10, v11);
            } else if (outmode == 1) {
                float w0 = gate[r0 / gg], w1 = gate[r1 / gg];
                if (w0 != 0.f) {
                    float2 o = *reinterpret_cast<const float2*>(&outF[(size_t)r0 * N + col]);
                    o.x += w0 * v00; o.y += w0 * v01;
                    *reinterpret_cast<float2*>(&outF[(size_t)r0 * N + col]) = o;
                }
                if (w1 != 0.f) {
                    float2 o = *reinterpret_cast<const float2*>(&outF[(size_t)r1 * N + col]);
                    o.x += w1 * v10; o.y += w1 * v11;
                    *reinterpret_cast<float2*>(&outF[(size_t)r1 * N + col]) = o;
                }
            } else {
                __half2 hp;
                hp.x = __float2half_rn(v00); hp.y = __float2half_rn(v01);
                *reinterpret_cast<__half2*>(&outH[(size_t)r0 * N + col]) = hp;
                hp.x = __float2half_rn(v10); hp.y = __float2half_rn(v11);
                *reinterpret_cast<__half2*>(&outH[(size_t)r1 * N + col]) = hp;
            }
        }
    }
}

// ---------------- launch ----------------
static inline int nblk(long long total, int t) { return (int)((total + t - 1) / t); }

extern "C" void kernel_launch(void* const* d_in, const int* in_sizes, int n_in,
                              void* d_out, int out_size) {
    const float* x   = (const float*)d_in[0];
    const int*   sel = (const int*)d_in[1];
    const float* rw  = (const float*)d_in[2];
    const float* wt0 = (const float*)d_in[3];  const float* bt0 = (const float*)d_in[4];
    const float* wp0 = (const float*)d_in[5];  const float* bp0 = (const float*)d_in[6];
    const float* wt1 = (const float*)d_in[7];  const float* bt1 = (const float*)d_in[8];
    const float* wp1 = (const float*)d_in[9];  const float* bp1 = (const float*)d_in[10];
    const float* wt2 = (const float*)d_in[11]; const float* bt2 = (const float*)d_in[12];
    const float* wp2 = (const float*)d_in[13]; const float* bp2 = (const float*)d_in[14];
    float* out = (float*)d_out;

    float *gate_d, *x336_d, *feat_d;
    __half *A1, *A2, *Bh, *Bl;
    cudaGetSymbolAddress((void**)&gate_d, g_gate);
    cudaGetSymbolAddress((void**)&x336_d, g_x336);
    cudaGetSymbolAddress((void**)&feat_d, g_feat);
    cudaGetSymbolAddress((void**)&A1, g_A1);
    cudaGetSymbolAddress((void**)&A2, g_A2);
    cudaGetSymbolAddress((void**)&Bh, g_Bh);
    cudaGetSymbolAddress((void**)&Bl, g_Bl);

    const int SMEM = 2 * 49152;
    cudaFuncSetAttribute(gemm_mma, cudaFuncAttributeMaxDynamicSharedMemorySize, SMEM);

    gate_kernel<<<1, 64>>>(sel, rw);
    cudaMemsetAsync(d_out, 0, (size_t)out_size * sizeof(float));
    resize_input_kernel<<<nblk(64LL * 3 * 336 * 336, 256), 256>>>(x);

    // =============== expert 0: g=32, Kt=588->640, C=1024 ===============
    weight_splitT<<<nblk(1024LL * 640, 256), 256>>>(wt0, 588, 1024, 640, Bh, Bl);
    im2col_half<448, 14, 32, 640><<<nblk(64LL * 1024 * 80, 256), 256>>>(x, gate_d, A1);
    gemm_mma<<<dim3(8, 512), 256, SMEM>>>(A1, Bh, Bl, bt0, 1024, 640,
                                          gate_d, 1024, 2, nullptr, A2);
    weight_splitT<<<nblk(1024LL * 1024, 256), 256>>>(wp0, 1024, 1024, 1024, Bh, Bl);
    gemm_mma<<<dim3(8, 512), 256, SMEM>>>(A2, Bh, Bl, bp0, 1024, 1024,
                                          gate_d, 1024, 1, out, nullptr);

    // =============== expert 1: g=24, Kt=588->640, C=768 ===============
    weight_splitT<<<nblk(768LL * 640, 256), 256>>>(wt1, 588, 768, 640, Bh, Bl);
    im2col_half<336, 14, 24, 640><<<nblk(64LL * 576 * 80, 256), 256>>>(x336_d, gate_d + 64, A1);
    gemm_mma<<<dim3(6, 288), 256, SMEM>>>(A1, Bh, Bl, bt1, 768, 640,
                                          gate_d + 64, 576, 0, feat_d, nullptr);
    resize_grid_half<24, 768><<<nblk(64LL * 1024 * 96, 256), 256>>>(feat_d, gate_d + 64, A2);
    weight_splitT<<<nblk(1024LL * 768, 256), 256>>>(wp1, 768, 1024, 768, Bh, Bl);
    gemm_mma<<<dim3(8, 512), 256, SMEM>>>(A2, Bh, Bl, bp1, 1024, 768,
                                          gate_d + 64, 1024, 1, out, nullptr);

    // =============== expert 2: g=14, Kt=3072, C=1152 ===============
    weight_splitT<<<nblk(1152LL * 3072, 256), 256>>>(wt2, 3072, 1152, 3072, Bh, Bl);
    im2col_half<448, 32, 14, 3072><<<nblk(64LL * 196 * 384, 256), 256>>>(x, gate_d + 128, A1);
    gemm_mma<<<dim3(9, 98), 256, SMEM>>>(A1, Bh, Bl, bt2, 1152, 3072,
                                         gate_d + 128, 196, 0, feat_d, nullptr);
    resize_grid_half<14, 1152><<<nblk(64LL * 1024 * 144, 256), 256>>>(feat_d, gate_d + 128, A2);
    weight_splitT<<<nblk(1024LL * 1152, 256), 256>>>(wp2, 1152, 1024, 1152, Bh, Bl);
    gemm_mma<<<dim3(8, 512), 256, SMEM>>>(A2, Bh, Bl, bp2, 1024, 1152,
                                          gate_d + 128, 1024, 1, out, nullptr);
}

// round 5
// speedup vs baseline: 7.2014x; 2.0700x over previous
#include <cuda_runtime.h>
#include <cuda_fp16.h>
#include <cstdint>
#include <math.h>

// ============================================================================
// VisionExperts via mma.sync (HMMA fp16, f32 accum), single-product GEMM.
// A and B both fp16-rounded (error ~2^-12 each side, ~4e-4 total vs 1e-3 gate).
// GEMM: 128x128 CTA tile, K-chunk 64, 8 warps (2x4), 3-stage cp.async pipeline,
// XOR-swizzled 128B smem rows, conflict-free ldmatrix.
// ============================================================================

// ---------------- scratch (device globals; no allocs) ----------------
__device__ float g_gate[3 * 64];
__device__ float g_x336[21676032];                   // expert-1 resized input
__device__ float g_feat[28311552];                   // tower fp32 out (e1/e2)
__device__ __align__(128) __half g_A1[41943040];     // tower A operand (fp16)
__device__ __align__(128) __half g_A2[75497472];     // projector A operand
__device__ __align__(128) __half g_B[3538944];       // weight fp16 (N-major)

// ---------------- helpers ----------------
__device__ __forceinline__ uint32_t smem_u32(const void* p) {
    uint32_t a;
    asm("{ .reg .u64 t; cvta.to.shared.u64 t, %1; cvt.u32.u64 %0, t; }" : "=r"(a) : "l"(p));
    return a;
}
__device__ __forceinline__ void cp16(uint32_t so, const void* g) {
    asm volatile("cp.async.cg.shared.global [%0], [%1], 16;" :: "r"(so), "l"(g));
}
__device__ __forceinline__ void ldm4(uint32_t* r, uint32_t addr) {
    asm volatile("ldmatrix.sync.aligned.m8n8.x4.shared.b16 {%0,%1,%2,%3}, [%4];"
                 : "=r"(r[0]), "=r"(r[1]), "=r"(r[2]), "=r"(r[3]) : "r"(addr));
}
__device__ __forceinline__ void mma_f16(float* d, const uint32_t* a, uint32_t b0, uint32_t b1) {
    asm volatile("mma.sync.aligned.m16n8k16.row.col.f32.f16.f16.f32 "
                 "{%0,%1,%2,%3}, {%4,%5,%6,%7}, {%8,%9}, {%0,%1,%2,%3};"
                 : "+f"(d[0]), "+f"(d[1]), "+f"(d[2]), "+f"(d[3])
                 : "r"(a[0]), "r"(a[1]), "r"(a[2]), "r"(a[3]), "r"(b0), "r"(b1));
}

// ---------------- gates ----------------
__global__ void gate_kernel(const int* __restrict__ sel, const float* __restrict__ rw) {
    int b = threadIdx.x;
    if (b >= 64) return;
    float w0 = 0.f, w1 = 0.f, w2 = 0.f;
#pragma unroll
    for (int k = 0; k < 2; k++) {
        int e = sel[b * 2 + k];
        float r = rw[b * 2 + k];
        w0 += (e == 0) ? r : 0.f;
        w1 += (e == 1) ? r : 0.f;
        w2 += (e == 2) ? r : 0.f;
    }
    g_gate[b] = w0; g_gate[64 + b] = w1; g_gate[128 + b] = w2;
}

// ---------------- input resize 448 -> 336 ----------------
__global__ void resize_input_kernel(const float* __restrict__ x) {
    long long idx = (long long)blockIdx.x * blockDim.x + threadIdx.x;
    const long long total = 64LL * 3 * 336 * 336;
    if (idx >= total) return;
    int ox = (int)(idx % 336);
    long long r = idx / 336;
    int oy = (int)(r % 336); r /= 336;
    int c = (int)(r % 3);
    int b = (int)(r / 3);
    if (g_gate[64 + b] == 0.f) return;
    const float sc = 447.0f / 335.0f;
    float ys = oy * sc, xs = ox * sc;
    int y0 = (int)floorf(ys); int y1 = min(y0 + 1, 447);
    int x0 = (int)floorf(xs); int x1 = min(x0 + 1, 447);
    float ty = ys - (float)y0, tx = xs - (float)x0;
    const float* p = x + ((long long)(b * 3 + c)) * 448 * 448;
    float a = p[y0 * 448 + x0], bv = p[y0 * 448 + x1];
    float cv = p[y1 * 448 + x0], dv = p[y1 * 448 + x1];
    float r0 = a * (1.f - ty) + cv * ty;
    float r1 = bv * (1.f - ty) + dv * ty;
    g_x336[idx] = r0 * (1.f - tx) + r1 * tx;
}

// ---------------- weight transpose: W[K,N] -> B[N,Kp] fp16 ----------------
__global__ void weight_halfT(const float* __restrict__ W, int K, int N, int Kp,
                             __half* __restrict__ B) {
    long long idx = (long long)blockIdx.x * blockDim.x + threadIdx.x;
    long long total = (long long)N * Kp;
    if (idx >= total) return;
    int k = (int)(idx % Kp);
    int n = (int)(idx / Kp);
    float v = (k < K) ? W[(long long)k * N + n] : 0.f;
    B[idx] = __float2half_rn(v);
}

// ---------------- im2col -> fp16 (templated; 8 elems/thread) ----------------
template <int S, int P, int G, int KP>
__global__ void im2col_half(const float* __restrict__ src, const float* __restrict__ gate,
                            __half* __restrict__ A) {
    constexpr int K = 3 * P * P;
    constexpr int GG = G * G;
    long long v8 = (long long)blockIdx.x * blockDim.x + threadIdx.x;
    const long long total8 = 64LL * GG * (KP / 8);
    if (v8 >= total8) return;
    int kc = (int)(v8 % (KP / 8));
    long long row = v8 / (KP / 8);
    int t = (int)(row % GG);
    int b = (int)(row / GG);
    if (gate[b] == 0.f) return;
    const int ty = t / G, tx = t % G;
    const float* sb = src + ((long long)b * 3) * S * S;
    __half h[8];
#pragma unroll
    for (int j = 0; j < 8; j++) {
        int k = kc * 8 + j;
        float v = 0.f;
        if (k < K) {
            int ch = k / (P * P);
            int rr = k - ch * (P * P);
            int py = rr / P, px = rr - py * P;
            v = sb[((long long)ch * S + (ty * P + py)) * S + (tx * P + px)];
        }
        h[j] = __float2half_rn(v);
    }
    *reinterpret_cast<uint4*>(&A[row * KP + kc * 8]) = *reinterpret_cast<uint4*>(h);
}

// ---------------- grid resize g->32 -> fp16 (templated; 8 ch/thread) --------
template <int G, int C>
__global__ void resize_grid_half(const float* __restrict__ feat, const float* __restrict__ gate,
                                 __half* __restrict__ A) {
    long long v8 = (long long)blockIdx.x * blockDim.x + threadIdx.x;
    const long long total8 = 64LL * 1024 * (C / 8);
    if (v8 >= total8) return;
    int cc = (int)(v8 % (C / 8));
    long long r = v8 / (C / 8);
    int ot = (int)(r % 1024);
    int b = (int)(r / 1024);
    if (gate[b] == 0.f) return;
    int oy = ot >> 5, ox = ot & 31;
    const float sc = (float)(G - 1) / 31.0f;
    float ys = oy * sc, xs = ox * sc;
    int y0 = (int)floorf(ys); int y1 = min(y0 + 1, G - 1);
    int x0 = (int)floorf(xs); int x1 = min(x0 + 1, G - 1);
    float ty = ys - (float)y0, tx = xs - (float)x0;
    const float* fb = feat + (long long)b * G * G * C + cc * 8;
    const float* p00 = fb + (long long)(y0 * G + x0) * C;
    const float* p01 = fb + (long long)(y0 * G + x1) * C;
    const float* p10 = fb + (long long)(y1 * G + x0) * C;
    const float* p11 = fb + (long long)(y1 * G + x1) * C;
    __half h[8];
#pragma unroll
    for (int j = 0; j < 8; j += 4) {
        float4 a = *reinterpret_cast<const float4*>(p00 + j);
        float4 bv = *reinterpret_cast<const float4*>(p01 + j);
        float4 cv = *reinterpret_cast<const float4*>(p10 + j);
        float4 dv = *reinterpret_cast<const float4*>(p11 + j);
        float r0, r1;
        r0 = a.x * (1.f - ty) + cv.x * ty; r1 = bv.x * (1.f - ty) + dv.x * ty;
        h[j + 0] = __float2half_rn(r0 * (1.f - tx) + r1 * tx);
        r0 = a.y * (1.f - ty) + cv.y * ty; r1 = bv.y * (1.f - ty) + dv.y * ty;
        h[j + 1] = __float2half_rn(r0 * (1.f - tx) + r1 * tx);
        r0 = a.z * (1.f - ty) + cv.z * ty; r1 = bv.z * (1.f - ty) + dv.z * ty;
        h[j + 2] = __float2half_rn(r0 * (1.f - tx) + r1 * tx);
        r0 = a.w * (1.f - ty) + cv.w * ty; r1 = bv.w * (1.f - ty) + dv.w * ty;
        h[j + 3] = __float2half_rn(r0 * (1.f - tx) + r1 * tx);
    }
    *reinterpret_cast<uint4*>(&A[((long long)(b * 1024 + ot)) * C + cc * 8]) =
        *reinterpret_cast<uint4*>(h);
}

// ---------------- HMMA GEMM: C = A @ B^T, fp32 accumulate ------------------
// outmode 0: outF = acc + bias
// outmode 1: outF += gate[row/gg] * (acc + bias)
// outmode 2: outH = half(acc + bias)
// M,N multiples of 128; Kp multiple of 64. 3-stage cp.async pipeline.
__global__ void __launch_bounds__(256) gemm_mma(
    const __half* __restrict__ A, const __half* __restrict__ B,
    const float* __restrict__ bias, int N, int Kp,
    const float* __restrict__ gate, int gg, int outmode,
    float* __restrict__ outF, __half* __restrict__ outH)
{
    const int row0 = blockIdx.y * 128;
    const int col0 = blockIdx.x * 128;
    {   // gated tile skip
        int b0 = row0 / gg, b1 = (row0 + 127) / gg;
        float gm = 0.f;
        for (int b = b0; b <= b1; b++) gm = fmaxf(gm, gate[b]);
        if (gm == 0.f) return;
    }

    extern __shared__ char smem[];
    const uint32_t S = smem_u32(smem);
    const int tid = threadIdx.x;
    const int wid = tid >> 5, lane = tid & 31;
    const int wm = (wid >> 2) * 64;     // warp m offset
    const int wn = (wid & 3) * 32;      // warp n offset
    const int NC = Kp >> 6;             // K chunks of 64

    // stage (32KB): A (16KB) | B (16KB); 128B rows, chunk j at (j^(r&7))
    auto prefetch = [&](int c) {
        uint32_t st = S + (uint32_t)(c % 3) * 32768u;
        int kt = c << 6;
#pragma unroll
        for (int i = 0; i < 8; i++) {
            int cid = tid + (i << 8);
            int isB = cid >> 10;           // uniform per warp per i
            int rem = cid & 1023;
            int r = rem >> 3, j = rem & 7;
            const __half* gp = (!isB ? A + (size_t)(row0 + r) * Kp
                                     : B + (size_t)(col0 + r) * Kp) + kt + j * 8;
            uint32_t so = st + (isB << 14) + r * 128 + ((j ^ (r & 7)) << 4);
            cp16(so, gp);
        }
        asm volatile("cp.async.commit_group;" ::: "memory");
    };

    float acc[4][4][4];
#pragma unroll
    for (int i = 0; i < 4; i++)
#pragma unroll
        for (int j = 0; j < 4; j++)
#pragma unroll
            for (int q = 0; q < 4; q++) acc[i][j][q] = 0.f;

    const int lrow = lane & 15;
    const int lchunk = lane >> 4;

    prefetch(0);
    if (NC > 1) prefetch(1);
    for (int c = 0; c < NC; c++) {
        if (c + 2 < NC) {
            prefetch(c + 2);
            asm volatile("cp.async.wait_group 2;" ::: "memory");
        } else if (c + 1 < NC) {
            asm volatile("cp.async.wait_group 1;" ::: "memory");
        } else {
            asm volatile("cp.async.wait_group 0;" ::: "memory");
        }
        __syncthreads();

        uint32_t SA = S + (uint32_t)(c % 3) * 32768u;
        uint32_t SB = SA + 16384u;

#pragma unroll
        for (int k = 0; k < 4; k++) {
            const int ch = 2 * k + lchunk;
            uint32_t b[2][4];
#pragma unroll
            for (int j2 = 0; j2 < 2; j2++) {
                int rb = wn + j2 * 16 + lrow;
                ldm4(b[j2], SB + rb * 128 + ((ch ^ (rb & 7)) << 4));
            }
#pragma unroll
            for (int i = 0; i < 4; i++) {
                int ra = wm + i * 16 + lrow;
                uint32_t a[4];
                ldm4(a, SA + ra * 128 + ((ch ^ (ra & 7)) << 4));
#pragma unroll
                for (int j2 = 0; j2 < 2; j2++) {
                    mma_f16(acc[i][2 * j2],     a, b[j2][0], b[j2][2]);
                    mma_f16(acc[i][2 * j2 + 1], a, b[j2][1], b[j2][3]);
                }
            }
        }
        __syncthreads();
    }

    // ---- epilogue ----
    const int grp = lane >> 2, qid = lane & 3;
#pragma unroll
    for (int i = 0; i < 4; i++) {
        int r0 = row0 + wm + i * 16 + grp;
        int r1 = r0 + 8;
#pragma unroll
        for (int j = 0; j < 4; j++) {
            int col = col0 + wn + j * 8 + qid * 2;
            float b0 = bias[col], b1 = bias[col + 1];
            float v00 = acc[i][j][0] + b0, v01 = acc[i][j][1] + b1;   // row r0
            float v10 = acc[i][j][2] + b0, v11 = acc[i][j][3] + b1;   // row r1
            if (outmode == 0) {
                *reinterpret_cast<float2*>(&outF[(size_t)r0 * N + col]) = make_float2(v00, v01);
                *reinterpret_cast<float2*>(&outF[(size_t)r1 * N + col]) = make_float2(v10, v11);
            } else if (outmode == 1) {
                float w0 = gate[r0 / gg], w1 = gate[r1 / gg];
                if (w0 != 0.f) {
                    float2 o = *reinterpret_cast<const float2*>(&outF[(size_t)r0 * N + col]);
                    o.x += w0 * v00; o.y += w0 * v01;
                    *reinterpret_cast<float2*>(&outF[(size_t)r0 * N + col]) = o;
                }
                if (w1 != 0.f) {
                    float2 o = *reinterpret_cast<const float2*>(&outF[(size_t)r1 * N + col]);
                    o.x += w1 * v10; o.y += w1 * v11;
                    *reinterpret_cast<float2*>(&outF[(size_t)r1 * N + col]) = o;
                }
            } else {
                __half2 hp;
                hp.x = __float2half_rn(v00); hp.y = __float2half_rn(v01);
                *reinterpret_cast<__half2*>(&outH[(size_t)r0 * N + col]) = hp;
                hp.x = __float2half_rn(v10); hp.y = __float2half_rn(v11);
                *reinterpret_cast<__half2*>(&outH[(size_t)r1 * N + col]) = hp;
            }
        }
    }
}

// ---------------- launch ----------------
static inline int nblk(long long total, int t) { return (int)((total + t - 1) / t); }

extern "C" void kernel_launch(void* const* d_in, const int* in_sizes, int n_in,
                              void* d_out, int out_size) {
    const float* x   = (const float*)d_in[0];
    const int*   sel = (const int*)d_in[1];
    const float* rw  = (const float*)d_in[2];
    const float* wt0 = (const float*)d_in[3];  const float* bt0 = (const float*)d_in[4];
    const float* wp0 = (const float*)d_in[5];  const float* bp0 = (const float*)d_in[6];
    const float* wt1 = (const float*)d_in[7];  const float* bt1 = (const float*)d_in[8];
    const float* wp1 = (const float*)d_in[9];  const float* bp1 = (const float*)d_in[10];
    const float* wt2 = (const float*)d_in[11]; const float* bt2 = (const float*)d_in[12];
    const float* wp2 = (const float*)d_in[13]; const float* bp2 = (const float*)d_in[14];
    float* out = (float*)d_out;

    float *gate_d, *x336_d, *feat_d;
    __half *A1, *A2, *B;
    cudaGetSymbolAddress((void**)&gate_d, g_gate);
    cudaGetSymbolAddress((void**)&x336_d, g_x336);
    cudaGetSymbolAddress((void**)&feat_d, g_feat);
    cudaGetSymbolAddress((void**)&A1, g_A1);
    cudaGetSymbolAddress((void**)&A2, g_A2);
    cudaGetSymbolAddress((void**)&B, g_B);

    const int SMEM = 3 * 32768;
    cudaFuncSetAttribute(gemm_mma, cudaFuncAttributeMaxDynamicSharedMemorySize, SMEM);

    gate_kernel<<<1, 64>>>(sel, rw);
    cudaMemsetAsync(d_out, 0, (size_t)out_size * sizeof(float));
    resize_input_kernel<<<nblk(64LL * 3 * 336 * 336, 256), 256>>>(x);

    // =============== expert 0: g=32, Kt=588->640, C=1024 ===============
    weight_halfT<<<nblk(1024LL * 640, 256), 256>>>(wt0, 588, 1024, 640, B);
    im2col_half<448, 14, 32, 640><<<nblk(64LL * 1024 * 80, 256), 256>>>(x, gate_d, A1);
    gemm_mma<<<dim3(8, 512), 256, SMEM>>>(A1, B, bt0, 1024, 640,
                                          gate_d, 1024, 2, nullptr, A2);
    weight_halfT<<<nblk(1024LL * 1024, 256), 256>>>(wp0, 1024, 1024, 1024, B);
    gemm_mma<<<dim3(8, 512), 256, SMEM>>>(A2, B, bp0, 1024, 1024,
                                          gate_d, 1024, 1, out, nullptr);

    // =============== expert 1: g=24, Kt=588->640, C=768 ===============
    weight_halfT<<<nblk(768LL * 640, 256), 256>>>(wt1, 588, 768, 640, B);
    im2col_half<336, 14, 24, 640><<<nblk(64LL * 576 * 80, 256), 256>>>(x336_d, gate_d + 64, A1);
    gemm_mma<<<dim3(6, 288), 256, SMEM>>>(A1, B, bt1, 768, 640,
                                          gate_d + 64, 576, 0, feat_d, nullptr);
    resize_grid_half<24, 768><<<nblk(64LL * 1024 * 96, 256), 256>>>(feat_d, gate_d + 64, A2);
    weight_halfT<<<nblk(1024LL * 768, 256), 256>>>(wp1, 768, 1024, 768, B);
    gemm_mma<<<dim3(8, 512), 256, SMEM>>>(A2, B, bp1, 1024, 768,
                                          gate_d + 64, 1024, 1, out, nullptr);

    // =============== expert 2: g=14, Kt=3072, C=1152 ===============
    weight_halfT<<<nblk(1152LL * 3072, 256), 256>>>(wt2, 3072, 1152, 3072, B);
    im2col_half<448, 32, 14, 3072><<<nblk(64LL * 196 * 384, 256), 256>>>(x, gate_d + 128, A1);
    gemm_mma<<<dim3(9, 98), 256, SMEM>>>(A1, B, bt2, 1152, 3072,
                                         gate_d + 128, 196, 0, feat_d, nullptr);
    resize_grid_half<14, 1152><<<nblk(64LL * 1024 * 144, 256), 256>>>(feat_d, gate_d + 128, A2);
    weight_halfT<<<nblk(1024LL * 1152, 256), 256>>>(wp2, 1152, 1024, 1152, B);
    gemm_mma<<<dim3(8, 512), 256, SMEM>>>(A2, B, bp2, 1024, 1152,
                                          gate_d + 128, 1024, 1, out, nullptr);
}